// round 16
// baseline (speedup 1.0000x reference)
#include <cuda_runtime.h>
#include <cuda_fp16.h>
#include <cstdint>

// Problem constants
#define T_ 2048
#define B_ 64
#define D_ 256
#define H_ 256
#define L_ 2
#define M_ (T_ * B_)       // 131072 GEMM rows per layer

// W image (single fp16): per (l, ntile 0..7): 4 kb-blocks,
// each block 128 n-rows x 64 k fp16 = 16KB, rows 128B, unit swz ((j^(row&7))<<4).
__device__ __align__(16) unsigned char g_W[(size_t)L_ * 8 * 4 * 16384]; // 1 MB
// A image (single fp16): per m-tile (128 rows): [kb0..3] 4 x 16KB = 64KB.
__device__ __align__(16) unsigned char g_A[(size_t)(M_ / 128) * 65536]; // 67 MB
__device__ __align__(16) float4 g_bias4[(size_t)L_ * B_ * H_];          // [l][b][h].(f,i,g,o)

// ---------------------------------------------------------------------------
// helpers
// ---------------------------------------------------------------------------
__device__ __forceinline__ uint32_t smem_u32(const void* p)
{
    uint32_t a;
    asm("{ .reg .u64 t; cvta.to.shared.u64 t, %1; cvt.u32.u64 %0, t; }" : "=r"(a) : "l"(p));
    return a;
}
__device__ __forceinline__ unsigned short fp16_bits(float v)
{
    __half h = __float2half_rn(v);
    return *reinterpret_cast<unsigned short*>(&h);
}
__device__ __forceinline__ uint32_t pack_fp16x2(float a, float b)
{
    __half2 h = __floats2half2_rn(a, b);
    return *reinterpret_cast<uint32_t*>(&h);
}
__device__ __forceinline__ float sigmoidf_(float x)
{
    return __fdividef(1.0f, 1.0f + __expf(-x));
}
__device__ __forceinline__ float tanhf_(float x)
{
    return 1.0f - __fdividef(2.0f, 1.0f + __expf(2.0f * x));
}

#define CP16(s, g) asm volatile("cp.async.cg.shared.global [%0], [%1], 16;" :: "r"(s), "l"(g))
#define CP_COMMIT() asm volatile("cp.async.commit_group;" ::: "memory")
#define CP_WAIT2() asm volatile("cp.async.wait_group 2;" ::: "memory")
#define CP_WAIT1() asm volatile("cp.async.wait_group 1;" ::: "memory")
#define CP_WAIT0() asm volatile("cp.async.wait_group 0;" ::: "memory")

#define LDSM4(r, addr) asm volatile( \
    "ldmatrix.sync.aligned.m8n8.x4.shared.b16 {%0,%1,%2,%3}, [%4];" \
    : "=r"((r)[0]), "=r"((r)[1]), "=r"((r)[2]), "=r"((r)[3]) : "r"(addr))

#define MMA(d, a, b0, b1) asm volatile( \
    "mma.sync.aligned.m16n8k16.row.col.f32.f16.f16.f32 " \
    "{%0,%1,%2,%3},{%4,%5,%6,%7},{%8,%9},{%0,%1,%2,%3};" \
    : "+f"((d)[0]), "+f"((d)[1]), "+f"((d)[2]), "+f"((d)[3]) \
    : "r"((a)[0]), "r"((a)[1]), "r"((a)[2]), "r"((a)[3]), "r"(b0), "r"(b1))

// ---------------------------------------------------------------------------
// Kernel 1: W -> single fp16 image, swizzled 16KB blocks (n = h*4+g interleave)
//   EXACTLY 65536 items (256 blocks): j:3 | nloc:7 | kb:2 | nt:3 | l:1
// ---------------------------------------------------------------------------
__global__ void __launch_bounds__(256) wprep_kernel(const float* __restrict__ W)
{
    int idx = blockIdx.x * 256 + threadIdx.x;      // 65536 total
    int j = idx & 7;
    int nloc = (idx >> 3) & 127;
    int kb = (idx >> 10) & 3;
    int nt = (idx >> 12) & 7;
    int l = (idx >> 15) & 1;

    int n = nt * 128 + nloc, g = n & 3, h = n >> 2;
    int k0 = kb * 64 + j * 8;
    const float* wp = W + ((size_t)(l * 4 + g) * 512 + k0) * 256 + h;

    unsigned short v[8];
#pragma unroll
    for (int i = 0; i < 8; i++)
        v[i] = fp16_bits(wp[(size_t)i * 256]);

    uint4 out;
    out.x = (uint32_t)v[0] | ((uint32_t)v[1] << 16);
    out.y = (uint32_t)v[2] | ((uint32_t)v[3] << 16);
    out.z = (uint32_t)v[4] | ((uint32_t)v[5] << 16);
    out.w = (uint32_t)v[6] | ((uint32_t)v[7] << 16);
    unsigned off = (unsigned)nloc * 128 + (((unsigned)j ^ ((unsigned)nloc & 7)) << 4);
    size_t blk = (size_t)(l * 8 + nt) * 4 + kb;
    *(uint4*)(g_W + blk * 16384 + off) = out;
}

// ---------------------------------------------------------------------------
// Kernel 2: A(fp32) -> single fp16 swizzled image g_A (layer 0 inputs only).
// ---------------------------------------------------------------------------
__global__ void __launch_bounds__(256) aprep_kernel(const float* __restrict__ A, int t_stride)
{
    int idx = blockIdx.x * 256 + threadIdx.x;      // 4,194,304
    int k8 = idx & 31;
    int m = idx >> 5;

    const float* gp = A + (size_t)(m >> 6) * t_stride + (size_t)(m & 63) * 256 + k8 * 8;
    float4 va = *(const float4*)gp;
    float4 vb = *(const float4*)(gp + 4);
    uint4 out;
    out.x = pack_fp16x2(va.x, va.y);
    out.y = pack_fp16x2(va.z, va.w);
    out.z = pack_fp16x2(vb.x, vb.y);
    out.w = pack_fp16x2(vb.z, vb.w);

    int mt = m >> 7, mloc = m & 127, kb = k8 >> 3, j = k8 & 7;
    size_t base = (size_t)mt * 65536 + (size_t)kb * 16384 + (size_t)mloc * 128 +
                  (((unsigned)j ^ ((unsigned)mloc & 7)) << 4);
    *(uint4*)(g_A + base) = out;
}

// ---------------------------------------------------------------------------
// Kernel 3: effective bias (exact fp32): b[l,g,h] + sum_j h0[l,b,j]*W[l,g,D+j,h]
// ---------------------------------------------------------------------------
__global__ void __launch_bounds__(256) bias_kernel(const float* __restrict__ h0,
                                                   const float* __restrict__ W,
                                                   const float* __restrict__ bb)
{
    int idx = blockIdx.x * 256 + threadIdx.x;      // 131072
    int g = idx & 3;
    int h = (idx >> 2) & 255;
    int b = (idx >> 10) & 63;
    int l = (idx >> 16) & 1;

    const float* h0p = h0 + (l * B_ + b) * H_;
    const float* wp  = W + ((size_t)(l * 4 + g) * 512 + 256) * 256 + h;
    float acc = bb[(l * 4 + g) * H_ + h];
#pragma unroll 8
    for (int j = 0; j < H_; j++)
        acc = fmaf(h0p[j], wp[(size_t)j * 256], acc);
    ((float*)g_bias4)[idx] = acc;
}

// ---------------------------------------------------------------------------
// Kernel 4: single-term fp16 HMMA GEMM + register-resident LSTM epilogue.
//   CTA: 128m x 128n, 256 thr = 8 warps (4m x 2n), warp tile 32x64.
//   4 chunks (kb 0..3) of [A 16KB | W 16KB] = 32KB, ring of 3, prefill 3.
//   Epilogue: shfl gate-exchange (lanes x <-> x^1) gives each thread one
//   (m,h) with all 4 gates; activations computed from registers, no staging.
//   2 CTAs/SM; grid: x = nt 0..7 (32 h each), y = mt 0..1023.
// ---------------------------------------------------------------------------
#define CHUNK_BYTES 32768u
#define SMEM_SZ 98304
#define B3(x) ((x) % 3)

__global__ void __launch_bounds__(256, 2)
gemm_kernel(const float* __restrict__ c0, int l,
            float* __restrict__ hn, float* __restrict__ cn,
            float* __restrict__ x_out, int write_a)
{
    extern __shared__ __align__(1024) unsigned char smem[];
    const int tid = threadIdx.x;
    const int bx = blockIdx.x;
    const int mt = blockIdx.y;
    const int m0 = mt * 128;
    const uint32_t su = smem_u32(smem);
    const int lane = tid & 31, wid = tid >> 5;
    const int wm = wid >> 1, wn = wid & 1;

    const unsigned char* gWb = g_W + (size_t)(l * 8 + bx) * 65536;
    const unsigned char* gAb = g_A + (size_t)mt * 65536;

#define ISSUE_CHUNK(kb, buf)                                                      \
    do {                                                                          \
        const unsigned char* sa = gAb + (kb) * 16384 + tid * 16;                  \
        const unsigned char* sb = gWb + (size_t)(kb) * 16384 + tid * 16;          \
        uint32_t da = su + (buf) * CHUNK_BYTES + tid * 16;                        \
        CP16(da, sa); CP16(da + 4096, sa + 4096);                                 \
        CP16(da + 8192, sa + 8192); CP16(da + 12288, sa + 12288);                 \
        CP16(da + 16384, sb); CP16(da + 20480, sb + 4096);                        \
        CP16(da + 24576, sb + 8192); CP16(da + 28672, sb + 12288);                \
        CP_COMMIT();                                                              \
    } while (0)

    // prologue: prefill chunks 0, 1, 2
    ISSUE_CHUNK(0, 0);
    ISSUE_CHUNK(1, 1);
    ISSUE_CHUNK(2, 2);

    // per-lane ldmatrix offsets
    uint32_t aoff[2], aswz[2], boff[4], bswz[4];
    const uint32_t ua = (uint32_t)(lane >> 4);
    const uint32_t ub = (uint32_t)((lane >> 3) & 1);
#pragma unroll
    for (int tm = 0; tm < 2; tm++) {
        uint32_t row = (uint32_t)(wm * 32 + tm * 16 + (lane & 15));
        aoff[tm] = row * 128u;
        aswz[tm] = row & 7u;
    }
#pragma unroll
    for (int tn = 0; tn < 4; tn++) {
        uint32_t row = (uint32_t)(wn * 64 + tn * 16 + (lane & 7) + ((lane >> 4) << 3));
        boff[tn] = row * 128u + 16384u;           // W region inside chunk
        bswz[tn] = row & 7u;
    }

    float acc[2][8][4];
#pragma unroll
    for (int i = 0; i < 2; i++)
#pragma unroll
        for (int j = 0; j < 8; j++)
#pragma unroll
            for (int q = 0; q < 4; q++) acc[i][j][q] = 0.0f;

    // mainloop: 4 kb-chunks (K = 256)
#pragma unroll 1
    for (int kb = 0; kb < 4; kb++) {
        if (kb == 0) { CP_WAIT2(); }
        else if (kb == 1) { CP_WAIT2(); }
        else if (kb == 2) { CP_WAIT1(); }
        else { CP_WAIT0(); }
        __syncthreads();

        const uint32_t bb = su + (uint32_t)B3(kb) * CHUNK_BYTES;

#pragma unroll
        for (int ks = 0; ks < 4; ks++) {
            uint32_t a[2][4], w[4][4];
            const uint32_t ka = (uint32_t)(ks * 2) + ua;
            const uint32_t kv = (uint32_t)(ks * 2) + ub;

#pragma unroll
            for (int tm = 0; tm < 2; tm++)
                LDSM4(a[tm], bb + aoff[tm] + ((ka ^ aswz[tm]) << 4));
#pragma unroll
            for (int tn = 0; tn < 4; tn++)
                LDSM4(w[tn], bb + boff[tn] + ((kv ^ bswz[tn]) << 4));
#pragma unroll
            for (int tm = 0; tm < 2; tm++)
#pragma unroll
                for (int tn = 0; tn < 4; tn++) {
                    MMA(acc[tm][tn * 2 + 0], a[tm], w[tn][0], w[tn][1]);
                    MMA(acc[tm][tn * 2 + 1], a[tm], w[tn][2], w[tn][3]);
                }
        }
        __syncthreads();

        if (kb == 0)
            ISSUE_CHUNK(3, 0);
    }

    // -----------------------------------------------------------------------
    // Register-resident LSTM epilogue via shfl gate-exchange.
    // Fragment: lane owns rows r=(lane>>2), r+8; cols c=(lane&3)*2, c+1.
    // n = h*4+g  =>  pair (lane, lane^1) holds the 4 gates of one h.
    // Exchange: even lane keeps row r (own f,i + partner g,o);
    //           odd lane keeps row r+8 (partner f,i + own g,o).
    // Each thread ends with one (m, h) per (tm, j): 16 outputs/thread.
    // -----------------------------------------------------------------------
    {
        const int lodd = lane & 1;
        const int m = m0 + wm * 32 + (lane >> 2) + lodd * 8;   // + tm*16
        const int b = m & 63;                                   // same for tm (m+16: b changes!)
        (void)b;

#pragma unroll
        for (int tm = 0; tm < 2; tm++) {
            const int mm = m + tm * 16;
            const int tt = mm >> 6, bb2 = mm & 63;
            const float* c0p = c0 + ((size_t)l * B_ + bb2) * H_;
            const float4* bp = g_bias4 + (size_t)(l * B_ + bb2) * H_;
            const size_t obase = ((size_t)tt * (L_ * B_) + (size_t)l * B_ + bb2) * H_;

#pragma unroll
            for (int j = 0; j < 8; j++) {
                float d0 = acc[tm][j][0], d1 = acc[tm][j][1];
                float d2 = acc[tm][j][2], d3 = acc[tm][j][3];
                float s0 = lodd ? d0 : d2;
                float s1 = lodd ? d1 : d3;
                float r0 = __shfl_xor_sync(0xffffffffu, s0, 1);
                float r1 = __shfl_xor_sync(0xffffffffu, s1, 1);
                float gf = lodd ? r0 : d0;
                float gi = lodd ? r1 : d1;
                float gg = lodd ? d2 : r0;
                float go = lodd ? d3 : r1;

                int h = bx * 32 + wn * 16 + j * 2 + ((lane >> 1) & 1);
                float4 bv = bp[h];
                float f  = sigmoidf_(gf + bv.x);
                float ii = sigmoidf_(gi + bv.y);
                float gt = tanhf_(gg + bv.z);
                float o  = sigmoidf_(go + bv.w);
                float cc = fmaf(f, c0p[h], ii * gt);
                float hv = o * tanhf_(cc);

                hn[obase + h] = hv;
                cn[obase + h] = cc;

                if (write_a) {
                    // fp16 A-image element (k = h) for layer 1
                    __half e = __float2half_rn(hv);
                    int mloc = mm - m0;
                    size_t base = (size_t)mt * 65536 + (size_t)(h >> 6) * 16384 +
                                  (size_t)mloc * 128 +
                                  ((((unsigned)(h >> 3) & 7u) ^ ((unsigned)mloc & 7u)) << 4) +
                                  (unsigned)(h & 7) * 2;
                    *(__half*)(g_A + base) = e;
                } else if (x_out) {
                    x_out[(size_t)mm * H_ + h] = hv;
                }
            }
        }
    }
#undef ISSUE_CHUNK
}

// ---------------------------------------------------------------------------
// Launch. Output layout: [ x (T*B*H) | h_n (T*L*B*H) | c_n (T*L*B*H) ]
// ---------------------------------------------------------------------------
extern "C" void kernel_launch(void* const* d_in, const int* in_sizes, int n_in,
                              void* d_out, int out_size)
{
    const float* inputs = (const float*)d_in[0];   // [T,B,D]
    const float* h0     = (const float*)d_in[1];   // [L,B,H]
    const float* c0     = (const float*)d_in[2];   // [L,B,H]
    const float* W      = (const float*)d_in[3];   // [L,4,D+H,H]
    const float* bb     = (const float*)d_in[4];   // [L,4,H]

    float* out   = (float*)d_out;
    float* x_out = out;
    float* hn    = out + (size_t)T_ * B_ * H_;
    float* cn    = hn + (size_t)T_ * L_ * B_ * H_;

    cudaFuncSetAttribute(gemm_kernel,
                         cudaFuncAttributeMaxDynamicSharedMemorySize, SMEM_SZ);

    wprep_kernel<<<256, 256>>>(W);        // exactly 65536 work items
    bias_kernel<<<512, 256>>>(h0, W, bb);
    aprep_kernel<<<16384, 256>>>(inputs, B_ * D_);

    dim3 grid(8, M_ / 128);
    // layer 0: epilogue also writes layer-1's fp16 A-image
    gemm_kernel<<<grid, 256, SMEM_SZ>>>(c0, 0, hn, cn, nullptr, 1);
    // layer 1: writes x
    gemm_kernel<<<grid, 256, SMEM_SZ>>>(c0, 1, hn, cn, x_out, 0);
}

// round 17
// speedup vs baseline: 1.3743x; 1.3743x over previous
#include <cuda_runtime.h>
#include <cuda_fp16.h>
#include <cstdint>

// Problem constants
#define T_ 2048
#define B_ 64
#define D_ 256
#define H_ 256
#define L_ 2
#define M_ (T_ * B_)       // 131072 GEMM rows per layer

// W image (single fp16): per (l, ntile 0..7): 4 kb-blocks,
// each block 128 n-rows x 64 k fp16 = 16KB, rows 128B, unit swz ((j^(row&7))<<4).
__device__ __align__(16) unsigned char g_W[(size_t)L_ * 8 * 4 * 16384]; // 1 MB
// A image (single fp16): per m-tile (128 rows): [kb0..3] 4 x 16KB = 64KB.
__device__ __align__(16) unsigned char g_A[(size_t)(M_ / 128) * 65536]; // 67 MB
__device__ __align__(16) float4 g_bias4[(size_t)L_ * B_ * H_];          // [l][b][h].(f,i,g,o)

// ---------------------------------------------------------------------------
// helpers
// ---------------------------------------------------------------------------
__device__ __forceinline__ uint32_t smem_u32(const void* p)
{
    uint32_t a;
    asm("{ .reg .u64 t; cvta.to.shared.u64 t, %1; cvt.u32.u64 %0, t; }" : "=r"(a) : "l"(p));
    return a;
}
__device__ __forceinline__ unsigned short fp16_bits(float v)
{
    __half h = __float2half_rn(v);
    return *reinterpret_cast<unsigned short*>(&h);
}
__device__ __forceinline__ uint32_t pack_fp16x2(float a, float b)
{
    __half2 h = __floats2half2_rn(a, b);
    return *reinterpret_cast<uint32_t*>(&h);
}
__device__ __forceinline__ float sigmoidf_(float x)
{
    return __fdividef(1.0f, 1.0f + __expf(-x));
}
__device__ __forceinline__ float tanhf_(float x)
{
    return 1.0f - __fdividef(2.0f, 1.0f + __expf(2.0f * x));
}

#define CP16(s, g) asm volatile("cp.async.cg.shared.global [%0], [%1], 16;" :: "r"(s), "l"(g))
#define CP_COMMIT() asm volatile("cp.async.commit_group;" ::: "memory")
#define CP_WAIT2() asm volatile("cp.async.wait_group 2;" ::: "memory")
#define CP_WAIT1() asm volatile("cp.async.wait_group 1;" ::: "memory")
#define CP_WAIT0() asm volatile("cp.async.wait_group 0;" ::: "memory")

#define LDSM4(r, addr) asm volatile( \
    "ldmatrix.sync.aligned.m8n8.x4.shared.b16 {%0,%1,%2,%3}, [%4];" \
    : "=r"((r)[0]), "=r"((r)[1]), "=r"((r)[2]), "=r"((r)[3]) : "r"(addr))

#define MMA(d, a, b0, b1) asm volatile( \
    "mma.sync.aligned.m16n8k16.row.col.f32.f16.f16.f32 " \
    "{%0,%1,%2,%3},{%4,%5,%6,%7},{%8,%9},{%0,%1,%2,%3};" \
    : "+f"((d)[0]), "+f"((d)[1]), "+f"((d)[2]), "+f"((d)[3]) \
    : "r"((a)[0]), "r"((a)[1]), "r"((a)[2]), "r"((a)[3]), "r"(b0), "r"(b1))

// ---------------------------------------------------------------------------
// Kernel 1: W -> single fp16 image, swizzled 16KB blocks (n = h*4+g interleave)
//   EXACTLY 65536 items (256 blocks): j:3 | nloc:7 | kb:2 | nt:3 | l:1
// ---------------------------------------------------------------------------
__global__ void __launch_bounds__(256) wprep_kernel(const float* __restrict__ W)
{
    int idx = blockIdx.x * 256 + threadIdx.x;      // 65536 total
    int j = idx & 7;
    int nloc = (idx >> 3) & 127;
    int kb = (idx >> 10) & 3;
    int nt = (idx >> 12) & 7;
    int l = (idx >> 15) & 1;

    int n = nt * 128 + nloc, g = n & 3, h = n >> 2;
    int k0 = kb * 64 + j * 8;
    const float* wp = W + ((size_t)(l * 4 + g) * 512 + k0) * 256 + h;

    unsigned short v[8];
#pragma unroll
    for (int i = 0; i < 8; i++)
        v[i] = fp16_bits(wp[(size_t)i * 256]);

    uint4 out;
    out.x = (uint32_t)v[0] | ((uint32_t)v[1] << 16);
    out.y = (uint32_t)v[2] | ((uint32_t)v[3] << 16);
    out.z = (uint32_t)v[4] | ((uint32_t)v[5] << 16);
    out.w = (uint32_t)v[6] | ((uint32_t)v[7] << 16);
    unsigned off = (unsigned)nloc * 128 + (((unsigned)j ^ ((unsigned)nloc & 7)) << 4);
    size_t blk = (size_t)(l * 8 + nt) * 4 + kb;
    *(uint4*)(g_W + blk * 16384 + off) = out;
}

// ---------------------------------------------------------------------------
// Kernel 2: A(fp32) -> single fp16 swizzled image g_A (layer 0 inputs only).
// ---------------------------------------------------------------------------
__global__ void __launch_bounds__(256) aprep_kernel(const float* __restrict__ A, int t_stride)
{
    int idx = blockIdx.x * 256 + threadIdx.x;      // 4,194,304
    int k8 = idx & 31;
    int m = idx >> 5;

    const float* gp = A + (size_t)(m >> 6) * t_stride + (size_t)(m & 63) * 256 + k8 * 8;
    float4 va = *(const float4*)gp;
    float4 vb = *(const float4*)(gp + 4);
    uint4 out;
    out.x = pack_fp16x2(va.x, va.y);
    out.y = pack_fp16x2(va.z, va.w);
    out.z = pack_fp16x2(vb.x, vb.y);
    out.w = pack_fp16x2(vb.z, vb.w);

    int mt = m >> 7, mloc = m & 127, kb = k8 >> 3, j = k8 & 7;
    size_t base = (size_t)mt * 65536 + (size_t)kb * 16384 + (size_t)mloc * 128 +
                  (((unsigned)j ^ ((unsigned)mloc & 7)) << 4);
    *(uint4*)(g_A + base) = out;
}

// ---------------------------------------------------------------------------
// Kernel 3: effective bias (exact fp32): b[l,g,h] + sum_j h0[l,b,j]*W[l,g,D+j,h]
// ---------------------------------------------------------------------------
__global__ void __launch_bounds__(256) bias_kernel(const float* __restrict__ h0,
                                                   const float* __restrict__ W,
                                                   const float* __restrict__ bb)
{
    int idx = blockIdx.x * 256 + threadIdx.x;      // 131072
    int g = idx & 3;
    int h = (idx >> 2) & 255;
    int b = (idx >> 10) & 63;
    int l = (idx >> 16) & 1;

    const float* h0p = h0 + (l * B_ + b) * H_;
    const float* wp  = W + ((size_t)(l * 4 + g) * 512 + 256) * 256 + h;
    float acc = bb[(l * 4 + g) * H_ + h];
#pragma unroll 8
    for (int j = 0; j < H_; j++)
        acc = fmaf(h0p[j], wp[(size_t)j * 256], acc);
    ((float*)g_bias4)[idx] = acc;
}

// ---------------------------------------------------------------------------
// Kernel 4: single-term fp16 HMMA GEMM, W-resident, 2 m-tiles per CTA.
//   CTA: 128m x 128n, 256 thr = 8 warps (4m x 2n), warp tile 32x64.
//   smem: W persistent 64KB (4 kb-blocks) + A ring 3 x 16KB = 112KB, 2 CTAs/SM.
//   Tile ti (mt = by + ti*512): A chunk kb -> ring buf B3(kb+ti).
//   Epilogue: shfl gate-exchange -> activations in regs -> compact postact
//   stage (hv 16KB in buf2, cc 16KB in buf0, XOR-swizzled) -> coalesced
//   float4 global writes.  Next tile's chunk0 copy is issued before the stage.
//   grid: x = nt 0..7 (32 h each), y = 0..511.
// ---------------------------------------------------------------------------
#define SM_RING 65536u
#define SMEM_SZ 114688
#define B3(x) ((x) % 3)

__global__ void __launch_bounds__(256, 2)
gemm_kernel(const float* __restrict__ c0, int l,
            float* __restrict__ hn, float* __restrict__ cn,
            float* __restrict__ x_out, int write_a)
{
    extern __shared__ __align__(1024) unsigned char smem[];
    const int tid = threadIdx.x;
    const int bx = blockIdx.x;
    const int by = blockIdx.y;
    const uint32_t su = smem_u32(smem);
    const int lane = tid & 31, wid = tid >> 5;
    const int wm = wid >> 1, wn = wid & 1;
    const int lodd = lane & 1;

    const unsigned char* gAb0 = g_A + (size_t)by * 65536;

#define ISSUE_A(mtX, kbX, bufX)                                                   \
    do {                                                                          \
        const unsigned char* sa = g_A + (size_t)(mtX) * 65536 +                   \
                                  (kbX) * 16384 + tid * 16;                       \
        uint32_t da = su + SM_RING + (uint32_t)(bufX) * 16384u + tid * 16;        \
        CP16(da, sa); CP16(da + 4096, sa + 4096);                                 \
        CP16(da + 8192, sa + 8192); CP16(da + 12288, sa + 12288);                 \
        CP_COMMIT();                                                              \
    } while (0)

    // prologue: W (64KB, one group) + tile0 chunks 0,1,2
    {
        const unsigned char* s = g_W + (size_t)(l * 8 + bx) * 65536 + tid * 16;
        uint32_t d = su + tid * 16;
#pragma unroll
        for (int j = 0; j < 16; j++) CP16(d + j * 4096, s + (size_t)j * 4096);
        CP_COMMIT();
    }
    ISSUE_A(by, 0, 0);
    ISSUE_A(by, 1, 1);
    ISSUE_A(by, 2, 2);

    // per-lane ldmatrix offsets
    uint32_t aoff[2], aswz[2], boff[4], bswz[4];
    const uint32_t ua = (uint32_t)(lane >> 4);
    const uint32_t ub = (uint32_t)((lane >> 3) & 1);
#pragma unroll
    for (int tm = 0; tm < 2; tm++) {
        uint32_t row = (uint32_t)(wm * 32 + tm * 16 + (lane & 15));
        aoff[tm] = row * 128u;
        aswz[tm] = row & 7u;
    }
#pragma unroll
    for (int tn = 0; tn < 4; tn++) {
        uint32_t row = (uint32_t)(wn * 64 + tn * 16 + (lane & 7) + ((lane >> 4) << 3));
        boff[tn] = row * 128u;
        bswz[tn] = row & 7u;
    }

    float* stage_hv = (float*)(smem + SM_RING + 32768u);   // ring buf2
    float* stage_cc = (float*)(smem + SM_RING);            // ring buf0

#pragma unroll 1
    for (int ti = 0; ti < 2; ti++) {
        const int mt = by + ti * 512;
        const int m0 = mt * 128;

        float acc[2][8][4];
#pragma unroll
        for (int i = 0; i < 2; i++)
#pragma unroll
            for (int j = 0; j < 8; j++)
#pragma unroll
                for (int q = 0; q < 4; q++) acc[i][j][q] = 0.0f;

        // mainloop: 4 kb-chunks (K = 256)
#pragma unroll 1
        for (int kb = 0; kb < 4; kb++) {
            if (kb < 2) { CP_WAIT2(); }
            else if (kb == 2) { CP_WAIT1(); }
            else { CP_WAIT0(); }
            __syncthreads();

            const uint32_t ab = su + SM_RING + (uint32_t)B3(kb + ti) * 16384u;
            const uint32_t wb = su + (uint32_t)kb * 16384u;

#pragma unroll
            for (int ks = 0; ks < 4; ks++) {
                uint32_t a[2][4], w[4][4];
                const uint32_t ka = (uint32_t)(ks * 2) + ua;
                const uint32_t kv = (uint32_t)(ks * 2) + ub;

#pragma unroll
                for (int tm = 0; tm < 2; tm++)
                    LDSM4(a[tm], ab + aoff[tm] + ((ka ^ aswz[tm]) << 4));
#pragma unroll
                for (int tn = 0; tn < 4; tn++)
                    LDSM4(w[tn], wb + boff[tn] + ((kv ^ bswz[tn]) << 4));
#pragma unroll
                for (int tm = 0; tm < 2; tm++)
#pragma unroll
                    for (int tn = 0; tn < 4; tn++) {
                        MMA(acc[tm][tn * 2 + 0], a[tm], w[tn][0], w[tn][1]);
                        MMA(acc[tm][tn * 2 + 1], a[tm], w[tn][2], w[tn][3]);
                    }
            }
            __syncthreads();

            if (kb == 0)
                ISSUE_A(mt, 3, B3(3 + ti));
        }

        // next tile's chunk 0 -> buf1 (B3(0+1)) before the epilogue
        if (ti == 0)
            ISSUE_A(by + 512, 0, 1);

        // ---- shfl gate-exchange + activations -> compact postact stage ----
#pragma unroll
        for (int tm = 0; tm < 2; tm++) {
            const int mm = m0 + wm * 32 + tm * 16 + (lane >> 2) + lodd * 8;
            const int bb2 = mm & 63;
            const int mloc = mm - m0;
            const float* c0p = c0 + ((size_t)l * B_ + bb2) * H_;
            const float4* bp = g_bias4 + (size_t)(l * B_ + bb2) * H_;

#pragma unroll
            for (int j = 0; j < 8; j++) {
                float d0 = acc[tm][j][0], d1 = acc[tm][j][1];
                float d2 = acc[tm][j][2], d3 = acc[tm][j][3];
                float s0 = lodd ? d0 : d2;
                float s1 = lodd ? d1 : d3;
                float r0 = __shfl_xor_sync(0xffffffffu, s0, 1);
                float r1 = __shfl_xor_sync(0xffffffffu, s1, 1);
                float gf = lodd ? r0 : d0;
                float gi = lodd ? r1 : d1;
                float gg = lodd ? d2 : r0;
                float go = lodd ? d3 : r1;

                int hloc = wn * 16 + j * 2 + ((lane >> 1) & 1);
                int h = bx * 32 + hloc;
                float4 bv = bp[h];
                float f  = sigmoidf_(gf + bv.x);
                float ii = sigmoidf_(gi + bv.y);
                float gt = tanhf_(gg + bv.z);
                float o  = sigmoidf_(go + bv.w);
                float cc = fmaf(f, c0p[h], ii * gt);
                float hv = o * tanhf_(cc);

                int sidx = mloc * 32 + (hloc ^ ((mloc & 7) << 2));
                stage_hv[sidx] = hv;
                stage_cc[sidx] = cc;
            }
        }
        __syncthreads();

        // ---- coalesced output from stage: 512 items = 128 rows x 4 h-groups ----
#pragma unroll
        for (int u = 0; u < 2; u++) {
            int item = u * 256 + tid;
            int hg = item & 3, mloc = item >> 2;
            int m = m0 + mloc;
            int t = m >> 6, b = m & 63;
            int hbase = bx * 32 + hg * 8;
            int sw = (mloc & 7) << 2;
            int sbase = mloc * 32;

            float4 hv0 = *(float4*)&stage_hv[sbase + ((hg * 8) ^ sw)];
            float4 hv1 = *(float4*)&stage_hv[sbase + ((hg * 8 + 4) ^ sw)];
            float4 cc0 = *(float4*)&stage_cc[sbase + ((hg * 8) ^ sw)];
            float4 cc1 = *(float4*)&stage_cc[sbase + ((hg * 8 + 4) ^ sw)];

            size_t ob = ((size_t)t * (L_ * B_) + (size_t)l * B_ + b) * H_ + hbase;
            *(float4*)&hn[ob]     = hv0;
            *(float4*)&hn[ob + 4] = hv1;
            *(float4*)&cn[ob]     = cc0;
            *(float4*)&cn[ob + 4] = cc1;

            if (write_a) {
                uint4 out;
                out.x = pack_fp16x2(hv0.x, hv0.y);
                out.y = pack_fp16x2(hv0.z, hv0.w);
                out.z = pack_fp16x2(hv1.x, hv1.y);
                out.w = pack_fp16x2(hv1.z, hv1.w);
                int k8 = hbase >> 3;
                int kb_a = k8 >> 3, j_a = k8 & 7;
                size_t base = (size_t)mt * 65536 + (size_t)kb_a * 16384 +
                              (size_t)mloc * 128 +
                              (((unsigned)j_a ^ ((unsigned)mloc & 7)) << 4);
                *(uint4*)(g_A + base) = out;
            } else if (x_out) {
                float* xp = x_out + (size_t)m * H_ + hbase;
                *(float4*)xp       = hv0;
                *(float4*)(xp + 4) = hv1;
            }
        }
        __syncthreads();

        // remaining chunks of the next tile
        if (ti == 0) {
            ISSUE_A(by + 512, 1, 2);
            ISSUE_A(by + 512, 2, 0);
        }
    }
#undef ISSUE_A
}

// ---------------------------------------------------------------------------
// Launch. Output layout: [ x (T*B*H) | h_n (T*L*B*H) | c_n (T*L*B*H) ]
// ---------------------------------------------------------------------------
extern "C" void kernel_launch(void* const* d_in, const int* in_sizes, int n_in,
                              void* d_out, int out_size)
{
    const float* inputs = (const float*)d_in[0];   // [T,B,D]
    const float* h0     = (const float*)d_in[1];   // [L,B,H]
    const float* c0     = (const float*)d_in[2];   // [L,B,H]
    const float* W      = (const float*)d_in[3];   // [L,4,D+H,H]
    const float* bb     = (const float*)d_in[4];   // [L,4,H]

    float* out   = (float*)d_out;
    float* x_out = out;
    float* hn    = out + (size_t)T_ * B_ * H_;
    float* cn    = hn + (size_t)T_ * L_ * B_ * H_;

    cudaFuncSetAttribute(gemm_kernel,
                         cudaFuncAttributeMaxDynamicSharedMemorySize, SMEM_SZ);

    wprep_kernel<<<256, 256>>>(W);        // exactly 65536 work items
    bias_kernel<<<512, 256>>>(h0, W, bb);
    aprep_kernel<<<16384, 256>>>(inputs, B_ * D_);

    dim3 grid(8, 512);
    // layer 0: epilogue also writes layer-1's fp16 A-image
    gemm_kernel<<<grid, 256, SMEM_SZ>>>(c0, 0, hn, cn, nullptr, 1);
    // layer 1: writes x
    gemm_kernel<<<grid, 256, SMEM_SZ>>>(c0, 1, hn, cn, x_out, 0);
}